// round 3
// baseline (speedup 1.0000x reference)
#include <cuda_runtime.h>
#include <math.h>
#include <stdint.h>

#define NTOK 16384          // BATCH * SEQ
#define SEQL 2048
#define NB   8
#define DM   384
#define DI   768
#define DS   16
#define DTR  24
#define XD   56             // DTR + 2*DS
#define XZW  1536           // 2*DI

// ---------------- scratch (static device memory; no allocation) ------------
__device__ float g_xn  [(size_t)NTOK * DM];
__device__ float g_xz  [(size_t)NTOK * XZW];
__device__ float g_xs  [(size_t)NTOK * DI];
__device__ float g_xdbl[(size_t)NTOK * XD];
__device__ float g_dt  [(size_t)NTOK * DI];
__device__ float g_y   [(size_t)NTOK * DI];
__device__ float g_h2  [(size_t)NTOK * DM];

// ---------------- layernorm: one block per token ---------------------------
__global__ void ln_kernel(const float* __restrict__ in,
                          const float* __restrict__ w,
                          const float* __restrict__ b,
                          float* __restrict__ out)
{
    int row = blockIdx.x;
    const float* x = in + (size_t)row * DM;
    int t = threadIdx.x;               // 128 threads, 3 elems each
    float v[3];
    float s = 0.f;
    #pragma unroll
    for (int i = 0; i < 3; i++) { v[i] = x[t + i * 128]; s += v[i]; }

    __shared__ float red[4];
    #pragma unroll
    for (int o = 16; o > 0; o >>= 1) s += __shfl_xor_sync(0xffffffffu, s, o);
    if ((t & 31) == 0) red[t >> 5] = s;
    __syncthreads();
    float mu = (red[0] + red[1] + red[2] + red[3]) * (1.f / 384.f);

    float q = 0.f;
    #pragma unroll
    for (int i = 0; i < 3; i++) { float d = v[i] - mu; q = fmaf(d, d, q); }
    #pragma unroll
    for (int o = 16; o > 0; o >>= 1) q += __shfl_xor_sync(0xffffffffu, q, o);
    __syncthreads();
    if ((t & 31) == 0) red[t >> 5] = q;
    __syncthreads();
    float var = (red[0] + red[1] + red[2] + red[3]) * (1.f / 384.f);
    float rs = rsqrtf(var + 1e-5f);

    float* o = out + (size_t)row * DM;
    #pragma unroll
    for (int i = 0; i < 3; i++) {
        int c = t + i * 128;
        o[c] = (v[i] - mu) * rs * w[c] + b[c];
    }
}

// ================= TF32 tensor-core NT GEMM (ldmatrix mainloop) =============
// C[m,n] = epi( sum_k A[m,k] * B[n,k] )
// BM=BN=128, BK=32, 256 threads (8 warps as 2x4), warp tile 64x32.
#define TBM 128
#define TBN 128
#define TBK 32
#define TSTRIDE 36                 // floats per smem row (conflict-free)
#define TBUF (TBM * TSTRIDE)       // floats per A (or B) buffer

__device__ __forceinline__ void cp_async16(uint32_t dst, const void* src, bool ok)
{
    int sz = ok ? 16 : 0;
    asm volatile("cp.async.cg.shared.global [%0], [%1], 16, %2;\n"
                 :: "r"(dst), "l"(src), "r"(sz));
}
__device__ __forceinline__ void cp_commit() {
    asm volatile("cp.async.commit_group;\n");
}
__device__ __forceinline__ void cp_wait1() {
    asm volatile("cp.async.wait_group 1;\n");
}
__device__ __forceinline__ void ldsm_x4(uint32_t addr, uint32_t& r0, uint32_t& r1,
                                        uint32_t& r2, uint32_t& r3)
{
    asm volatile("ldmatrix.sync.aligned.m8n8.x4.shared.b16 {%0,%1,%2,%3}, [%4];\n"
                 : "=r"(r0), "=r"(r1), "=r"(r2), "=r"(r3) : "r"(addr));
}

// epi: 0 = none, 1 = softplus(v + bias[n]), 2 = v + resid[m*ldr+n], store flipped
__global__ void __launch_bounds__(256, 2)
gemm_tf32(const float* __restrict__ A, int lda,
          const float* __restrict__ B, int ldb,
          float* __restrict__ C, int ldc,
          const float* __restrict__ bias,
          const float* __restrict__ resid, int ldr,
          int M, int N, int K, int epi)
{
    extern __shared__ float smem[];
    float* AsB = smem;              // 2 buffers A
    float* BsB = smem + 2 * TBUF;   // 2 buffers B

    int tid  = threadIdx.x;
    int lane = tid & 31;
    int warp = tid >> 5;
    int gid  = lane >> 2;      // 0..7
    int tig  = lane & 3;       // 0..3
    int wm   = (warp >> 2) * 64;   // 0/64
    int wn   = (warp & 3) * 32;    // 0/32/64/96

    int m0 = blockIdx.y * TBM;
    int n0 = blockIdx.x * TBN;
    int nc = (K + TBK - 1) / TBK;

    uint32_t smem_u = (uint32_t)__cvta_generic_to_shared(smem);

    // ldmatrix address bases (bytes)
    int ar = lane & 15, ahi = lane >> 4;   // A: rows r, half-col select
    uint32_t aBase = smem_u + (uint32_t)(((wm + ar) * TSTRIDE + ahi * 4) * 4);
    int bq = lane >> 3;                    // B: quad 0..3
    uint32_t bBase = smem_u + (uint32_t)(2 * TBUF * 4)
                   + (uint32_t)((((wn + (bq >> 1) * 8 + (lane & 7)) * TSTRIDE)
                                 + (bq & 1) * 4) * 4);

    float acc[4][4][4];
    #pragma unroll
    for (int i = 0; i < 4; i++)
        #pragma unroll
        for (int j = 0; j < 4; j++)
            #pragma unroll
            for (int c = 0; c < 4; c++) acc[i][j][c] = 0.f;

    auto load_tiles = [&](int buf, int chunk) {
        int k0 = chunk * TBK;
        float* Asb = AsB + buf * TBUF;
        float* Bsb = BsB + buf * TBUF;
        #pragma unroll
        for (int it = 0; it < 4; it++) {
            int idx = tid + it * 256;
            int m  = idx >> 3;
            int k4 = idx & 7;
            int gk = k0 + k4 * 4;
            bool kok = (gk < K);
            {
                int gm = m0 + m;
                const void* src = kok ? (const void*)(A + (size_t)gm * lda + gk)
                                      : (const void*)A;
                uint32_t dst = (uint32_t)__cvta_generic_to_shared(
                                    Asb + m * TSTRIDE + k4 * 4);
                cp_async16(dst, src, kok);
            }
            {
                int gn = n0 + m;
                bool ok = kok && (gn < N);
                const void* src = ok ? (const void*)(B + (size_t)gn * ldb + gk)
                                     : (const void*)B;
                uint32_t dst = (uint32_t)__cvta_generic_to_shared(
                                    Bsb + m * TSTRIDE + k4 * 4);
                cp_async16(dst, src, ok);
            }
        }
    };

    load_tiles(0, 0);
    cp_commit();

    for (int c = 0; c < nc; c++) {
        if (c + 1 < nc) load_tiles((c + 1) & 1, c + 1);
        cp_commit();
        cp_wait1();
        __syncthreads();

        uint32_t bufOff = (uint32_t)((c & 1) * TBUF * 4);
        uint32_t aB = aBase + bufOff;
        uint32_t bB = bBase + bufOff;

        #pragma unroll
        for (int kk = 0; kk < 4; kk++) {
            uint32_t kOff = kk * 32;   // 8 tf32 = 32 bytes
            uint32_t af[4][4];
            #pragma unroll
            for (int mi = 0; mi < 4; mi++)
                ldsm_x4(aB + (uint32_t)(mi * 16 * TSTRIDE * 4) + kOff,
                        af[mi][0], af[mi][1], af[mi][2], af[mi][3]);
            uint32_t bf[4][2];
            #pragma unroll
            for (int p = 0; p < 2; p++)
                ldsm_x4(bB + (uint32_t)(p * 16 * TSTRIDE * 4) + kOff,
                        bf[2*p][0], bf[2*p][1], bf[2*p+1][0], bf[2*p+1][1]);
            #pragma unroll
            for (int mi = 0; mi < 4; mi++)
                #pragma unroll
                for (int ni = 0; ni < 4; ni++) {
                    asm volatile(
                        "mma.sync.aligned.m16n8k8.row.col.f32.tf32.tf32.f32 "
                        "{%0,%1,%2,%3}, {%4,%5,%6,%7}, {%8,%9}, {%0,%1,%2,%3};\n"
                        : "+f"(acc[mi][ni][0]), "+f"(acc[mi][ni][1]),
                          "+f"(acc[mi][ni][2]), "+f"(acc[mi][ni][3])
                        : "r"(af[mi][0]), "r"(af[mi][1]),
                          "r"(af[mi][2]), "r"(af[mi][3]),
                          "r"(bf[ni][0]), "r"(bf[ni][1]));
                }
        }
        __syncthreads();
    }

    // epilogue
    #pragma unroll
    for (int mi = 0; mi < 4; mi++) {
        int r0 = m0 + wm + mi * 16 + gid;
        #pragma unroll
        for (int ni = 0; ni < 4; ni++) {
            int cbase = n0 + wn + ni * 8 + tig * 2;
            #pragma unroll
            for (int half = 0; half < 2; half++) {
                int row = r0 + half * 8;
                if (row >= M) continue;
                int rowS = (epi == 2) ? (row ^ (SEQL - 1)) : row;  // fused flip
                #pragma unroll
                for (int cc = 0; cc < 2; cc++) {
                    int col = cbase + cc;
                    if (col >= N) continue;
                    float v = acc[mi][ni][half * 2 + cc];
                    if (epi == 1) {
                        v += bias[col];
                        v = fmaxf(v, 0.f) + log1pf(expf(-fabsf(v)));
                    } else if (epi == 2) {
                        v += resid[(size_t)row * ldr + col];
                    }
                    C[(size_t)rowS * ldc + col] = v;
                }
            }
        }
    }
}

// ---------------- causal depthwise conv (k=4) + SiLU: 4 tokens/thread ------
__global__ void conv_silu_kernel(const float* __restrict__ xz,
                                 const float* __restrict__ w,
                                 const float* __restrict__ b,
                                 float* __restrict__ out)
{
    int idx = blockIdx.x * blockDim.x + threadIdx.x;   // over (NTOK/4)*DI
    if (idx >= (NTOK / 4) * DI) return;
    int d  = idx % DI;
    int rq = idx / DI;
    int l0 = (rq & (SEQL / 4 - 1)) * 4;
    int r0 = (rq / (SEQL / 4)) * SEQL + l0;

    float w0 = w[d*4+0], w1 = w[d*4+1], w2 = w[d*4+2], w3 = w[d*4+3];
    float bb = b[d];

    float v[7];
    #pragma unroll
    for (int j = 0; j < 7; j++) {
        int li = l0 - 3 + j;
        v[j] = (li >= 0) ? xz[(size_t)(r0 - 3 + j) * XZW + d] : 0.f;
    }
    #pragma unroll
    for (int t = 0; t < 4; t++) {
        float acc = bb;
        acc = fmaf(v[t],     w0, acc);
        acc = fmaf(v[t + 1], w1, acc);
        acc = fmaf(v[t + 2], w2, acc);
        acc = fmaf(v[t + 3], w3, acc);
        out[(size_t)(r0 + t) * DI + d] = acc / (1.f + __expf(-acc));
    }
}

// ---------------- selective scan + fused gate -------------------------------
// 16 lanes per (b,d); lane n==0 writes y = (sum h*C + xs*Dp) * silu(z)
__global__ void scan_kernel(const float* __restrict__ dt,
                            const float* __restrict__ xs,
                            const float* __restrict__ xdbl,
                            const float* __restrict__ A_log,
                            const float* __restrict__ xz,
                            const float* __restrict__ Dp,
                            float* __restrict__ y)
{
    int b = blockIdx.y;
    int d = blockIdx.x * 16 + (threadIdx.x >> 4);
    int n = threadIdx.x & 15;

    float Adn = -__expf(A_log[d * DS + n]);
    float Dpd = Dp[d];

    size_t rbase = (size_t)b * SEQL;
    const float* dtp = dt   + rbase * DI + d;
    const float* xsp = xs   + rbase * DI + d;
    const float* Bp  = xdbl + rbase * XD + DTR + n;
    const float* Cp  = xdbl + rbase * XD + DTR + DS + n;
    const float* zp  = xz   + rbase * XZW + DI + d;
    float*       yp  = y    + rbase * DI + d;

    float h = 0.f;
    #pragma unroll 2
    for (int l = 0; l < SEQL; l++) {
        float dtv = __ldg(dtp); dtp += DI;
        float xv  = __ldg(xsp); xsp += DI;
        float Bv  = __ldg(Bp);  Bp  += XD;
        float Cv  = __ldg(Cp);  Cp  += XD;
        float a = __expf(dtv * Adn);
        h = fmaf(a, h, dtv * xv * Bv);
        float p = h * Cv;
        p += __shfl_xor_sync(0xffffffffu, p, 8);
        p += __shfl_xor_sync(0xffffffffu, p, 4);
        p += __shfl_xor_sync(0xffffffffu, p, 2);
        p += __shfl_xor_sync(0xffffffffu, p, 1);
        if (n == 0) {
            float z = *zp;
            float s = z / (1.f + __expf(-z));
            *yp = fmaf(xv, Dpd, p) * s;
        }
        zp += XZW;
        yp += DI;
    }
}

// ---------------- launcher ---------------------------------------------------
extern "C" void kernel_launch(void* const* d_in, const int* in_sizes, int n_in,
                              void* d_out, int out_size)
{
    const float* x        = (const float*)d_in[0];
    const float* norm_w   = (const float*)d_in[1];
    const float* norm_b   = (const float*)d_in[2];
    const float* in_proj  = (const float*)d_in[3];
    const float* conv_w   = (const float*)d_in[4];
    const float* conv_b   = (const float*)d_in[5];
    const float* x_proj   = (const float*)d_in[6];
    const float* dt_w     = (const float*)d_in[7];
    const float* dt_b     = (const float*)d_in[8];
    const float* A_log    = (const float*)d_in[9];
    const float* Dp       = (const float*)d_in[10];
    const float* out_proj = (const float*)d_in[11];

    float *xn, *xz, *xs, *xdbl, *dt, *y, *h2;
    cudaGetSymbolAddress((void**)&xn,   g_xn);
    cudaGetSymbolAddress((void**)&xz,   g_xz);
    cudaGetSymbolAddress((void**)&xs,   g_xs);
    cudaGetSymbolAddress((void**)&xdbl, g_xdbl);
    cudaGetSymbolAddress((void**)&dt,   g_dt);
    cudaGetSymbolAddress((void**)&y,    g_y);
    cudaGetSymbolAddress((void**)&h2,   g_h2);

    const int SMEM_T = 2 * 2 * TBUF * (int)sizeof(float);   // 73728 B
    static int attr_set = 0;
    if (!attr_set) {
        cudaFuncSetAttribute(gemm_tf32,
                             cudaFuncAttributeMaxDynamicSharedMemorySize, SMEM_T);
        attr_set = 1;
    }

    const int EW = 256;

    for (int i = 0; i < 2; i++) {
        const float* cur = (i == 0) ? x : h2;
        float* nxt = (i == 0) ? h2 : (float*)d_out;

        // 1. layernorm
        ln_kernel<<<NTOK, 128>>>(cur, norm_w + i * DM, norm_b + i * DM, xn);

        // 2. xz = xn @ in_proj^T   (M=16384, N=1536, K=384)
        {
            dim3 g(XZW / TBN, NTOK / TBM);
            gemm_tf32<<<g, 256, SMEM_T>>>(xn, DM,
                                          in_proj + (size_t)i * XZW * DM, DM,
                                          xz, XZW, nullptr, nullptr, 0,
                                          NTOK, XZW, DM, 0);
        }

        // 3. xs = silu(causal_conv(xz[:, :768]))
        conv_silu_kernel<<<((NTOK / 4) * DI + EW - 1) / EW, EW>>>(
            xz, conv_w + (size_t)i * DI * 4, conv_b + i * DI, xs);

        // 4. xdbl = xs @ x_proj^T  (M=16384, N=56, K=768)  [tensor, masked]
        {
            dim3 g(1, NTOK / TBM);
            gemm_tf32<<<g, 256, SMEM_T>>>(xs, DI,
                                          x_proj + (size_t)i * XD * DI, DI,
                                          xdbl, XD, nullptr, nullptr, 0,
                                          NTOK, XD, DI, 0);
        }

        // 5. dt = softplus(xdbl[:, :24] @ dt_w^T + dt_b)  (N=768, K=24)
        {
            dim3 g(DI / TBN, NTOK / TBM);
            gemm_tf32<<<g, 256, SMEM_T>>>(xdbl, XD,
                                          dt_w + (size_t)i * DI * DTR, DTR,
                                          dt, DI, dt_b + i * DI, nullptr, 0,
                                          NTOK, DI, DTR, 1);
        }

        // 6. selective scan + gate -> y
        {
            dim3 g(DI / 16, NB);
            scan_kernel<<<g, 256>>>(dt, xs, xdbl,
                                    A_log + (size_t)i * DI * DS,
                                    xz, Dp + i * DI, y);
        }

        // 7. out = flip(y @ out_proj^T + cur)  (N=384, K=768) [flip fused]
        {
            dim3 g(DM / TBN, NTOK / TBM);
            gemm_tf32<<<g, 256, SMEM_T>>>(y, DI,
                                          out_proj + (size_t)i * DM * DI, DI,
                                          nxt, DM, nullptr, cur, DM,
                                          NTOK, DM, DI, 2);
        }
    }
}

// round 4
// speedup vs baseline: 3.1210x; 3.1210x over previous
#include <cuda_runtime.h>
#include <math.h>
#include <stdint.h>

#define NTOK 16384          // BATCH * SEQ
#define SEQL 2048
#define NB   8
#define DM   384
#define DI   768
#define DS   16
#define DTR  24
#define XD   56             // DTR + 2*DS
#define XZW  1536           // 2*DI

// ---------------- scratch (static device memory; no allocation) ------------
__device__ float g_xn  [(size_t)NTOK * DM];
__device__ float g_xz  [(size_t)NTOK * XZW];
__device__ float g_xs  [(size_t)NTOK * DI];
__device__ float g_xdbl[(size_t)NTOK * XD];
__device__ float g_dt  [(size_t)NTOK * DI];
__device__ float g_y   [(size_t)NTOK * DI];
__device__ float g_h1  [(size_t)NTOK * DM];
__device__ float g_h2  [(size_t)NTOK * DM];

// ---------------- layernorm: one block per token ---------------------------
__global__ void ln_kernel(const float* __restrict__ in,
                          const float* __restrict__ w,
                          const float* __restrict__ b,
                          float* __restrict__ out)
{
    int row = blockIdx.x;
    const float* x = in + (size_t)row * DM;
    int t = threadIdx.x;               // 128 threads, 3 elems each
    float v[3];
    float s = 0.f;
    #pragma unroll
    for (int i = 0; i < 3; i++) { v[i] = x[t + i * 128]; s += v[i]; }

    __shared__ float red[4];
    #pragma unroll
    for (int o = 16; o > 0; o >>= 1) s += __shfl_xor_sync(0xffffffffu, s, o);
    if ((t & 31) == 0) red[t >> 5] = s;
    __syncthreads();
    float mu = (red[0] + red[1] + red[2] + red[3]) * (1.f / 384.f);

    float q = 0.f;
    #pragma unroll
    for (int i = 0; i < 3; i++) { float d = v[i] - mu; q = fmaf(d, d, q); }
    #pragma unroll
    for (int o = 16; o > 0; o >>= 1) q += __shfl_xor_sync(0xffffffffu, q, o);
    __syncthreads();
    if ((t & 31) == 0) red[t >> 5] = q;
    __syncthreads();
    float var = (red[0] + red[1] + red[2] + red[3]) * (1.f / 384.f);
    float rs = rsqrtf(var + 1e-5f);

    float* o = out + (size_t)row * DM;
    #pragma unroll
    for (int i = 0; i < 3; i++) {
        int c = t + i * 128;
        o[c] = (v[i] - mu) * rs * w[c] + b[c];
    }
}

// ================= TF32 tensor-core NT GEMM (ldmatrix mainloop) =============
// C[m,n] = epi( sum_k A[m,k] * B[n,k] )
// BM=BN=128, BK=32, 256 threads (8 warps as 2x4), warp tile 64x32.
#define TBM 128
#define TBN 128
#define TBK 32
#define TSTRIDE 36                 // floats per smem row (conflict-free)
#define TBUF (TBM * TSTRIDE)       // floats per A (or B) buffer

__device__ __forceinline__ void cp_async16(uint32_t dst, const void* src, bool ok)
{
    int sz = ok ? 16 : 0;
    asm volatile("cp.async.cg.shared.global [%0], [%1], 16, %2;\n"
                 :: "r"(dst), "l"(src), "r"(sz));
}
__device__ __forceinline__ void cp_commit() {
    asm volatile("cp.async.commit_group;\n");
}
__device__ __forceinline__ void cp_wait1() {
    asm volatile("cp.async.wait_group 1;\n");
}
__device__ __forceinline__ void ldsm_x4(uint32_t addr, uint32_t& r0, uint32_t& r1,
                                        uint32_t& r2, uint32_t& r3)
{
    asm volatile("ldmatrix.sync.aligned.m8n8.x4.shared.b16 {%0,%1,%2,%3}, [%4];\n"
                 : "=r"(r0), "=r"(r1), "=r"(r2), "=r"(r3) : "r"(addr));
}

// epi: 0 = none, 1 = softplus(v + bias[n]), 2 = v + resid[m*ldr+n]
__global__ void __launch_bounds__(256, 2)
gemm_tf32(const float* __restrict__ A, int lda,
          const float* __restrict__ B, int ldb,
          float* __restrict__ C, int ldc,
          const float* __restrict__ bias,
          const float* __restrict__ resid, int ldr,
          int M, int N, int K, int epi)
{
    extern __shared__ float smem[];
    float* AsB = smem;              // 2 buffers A
    float* BsB = smem + 2 * TBUF;   // 2 buffers B

    int tid  = threadIdx.x;
    int lane = tid & 31;
    int warp = tid >> 5;
    int gid  = lane >> 2;      // 0..7
    int tig  = lane & 3;       // 0..3
    int wm   = (warp >> 2) * 64;   // 0/64
    int wn   = (warp & 3) * 32;    // 0/32/64/96

    int m0 = blockIdx.y * TBM;
    int n0 = blockIdx.x * TBN;
    int nc = (K + TBK - 1) / TBK;

    uint32_t smem_u = (uint32_t)__cvta_generic_to_shared(smem);

    // ldmatrix address bases (bytes)
    int ar = lane & 15, ahi = lane >> 4;   // A: rows, half-col select
    uint32_t aBase = smem_u + (uint32_t)(((wm + ar) * TSTRIDE + ahi * 4) * 4);
    int bq = lane >> 3;                    // B: quad 0..3
    uint32_t bBase = smem_u + (uint32_t)(2 * TBUF * 4)
                   + (uint32_t)((((wn + (bq >> 1) * 8 + (lane & 7)) * TSTRIDE)
                                 + (bq & 1) * 4) * 4);

    float acc[4][4][4];
    #pragma unroll
    for (int i = 0; i < 4; i++)
        #pragma unroll
        for (int j = 0; j < 4; j++)
            #pragma unroll
            for (int c = 0; c < 4; c++) acc[i][j][c] = 0.f;

    auto load_tiles = [&](int buf, int chunk) {
        int k0 = chunk * TBK;
        float* Asb = AsB + buf * TBUF;
        float* Bsb = BsB + buf * TBUF;
        #pragma unroll
        for (int it = 0; it < 4; it++) {
            int idx = tid + it * 256;
            int m  = idx >> 3;
            int k4 = idx & 7;
            int gk = k0 + k4 * 4;
            bool kok = (gk < K);
            {
                int gm = m0 + m;
                const void* src = kok ? (const void*)(A + (size_t)gm * lda + gk)
                                      : (const void*)A;
                uint32_t dst = (uint32_t)__cvta_generic_to_shared(
                                    Asb + m * TSTRIDE + k4 * 4);
                cp_async16(dst, src, kok);
            }
            {
                int gn = n0 + m;
                bool ok = kok && (gn < N);
                const void* src = ok ? (const void*)(B + (size_t)gn * ldb + gk)
                                     : (const void*)B;
                uint32_t dst = (uint32_t)__cvta_generic_to_shared(
                                    Bsb + m * TSTRIDE + k4 * 4);
                cp_async16(dst, src, ok);
            }
        }
    };

    load_tiles(0, 0);
    cp_commit();

    for (int c = 0; c < nc; c++) {
        if (c + 1 < nc) load_tiles((c + 1) & 1, c + 1);
        cp_commit();
        cp_wait1();
        __syncthreads();

        uint32_t bufOff = (uint32_t)((c & 1) * TBUF * 4);
        uint32_t aB = aBase + bufOff;
        uint32_t bB = bBase + bufOff;

        #pragma unroll
        for (int kk = 0; kk < 4; kk++) {
            uint32_t kOff = kk * 32;   // 8 tf32 = 32 bytes
            uint32_t af[4][4];
            #pragma unroll
            for (int mi = 0; mi < 4; mi++)
                ldsm_x4(aB + (uint32_t)(mi * 16 * TSTRIDE * 4) + kOff,
                        af[mi][0], af[mi][1], af[mi][2], af[mi][3]);
            uint32_t bf[4][2];
            #pragma unroll
            for (int p = 0; p < 2; p++)
                ldsm_x4(bB + (uint32_t)(p * 16 * TSTRIDE * 4) + kOff,
                        bf[2*p][0], bf[2*p][1], bf[2*p+1][0], bf[2*p+1][1]);
            #pragma unroll
            for (int mi = 0; mi < 4; mi++)
                #pragma unroll
                for (int ni = 0; ni < 4; ni++) {
                    asm volatile(
                        "mma.sync.aligned.m16n8k8.row.col.f32.tf32.tf32.f32 "
                        "{%0,%1,%2,%3}, {%4,%5,%6,%7}, {%8,%9}, {%0,%1,%2,%3};\n"
                        : "+f"(acc[mi][ni][0]), "+f"(acc[mi][ni][1]),
                          "+f"(acc[mi][ni][2]), "+f"(acc[mi][ni][3])
                        : "r"(af[mi][0]), "r"(af[mi][1]),
                          "r"(af[mi][2]), "r"(af[mi][3]),
                          "r"(bf[ni][0]), "r"(bf[ni][1]));
                }
        }
        __syncthreads();
    }

    // epilogue
    #pragma unroll
    for (int mi = 0; mi < 4; mi++) {
        int r0 = m0 + wm + mi * 16 + gid;
        #pragma unroll
        for (int ni = 0; ni < 4; ni++) {
            int cbase = n0 + wn + ni * 8 + tig * 2;
            #pragma unroll
            for (int half = 0; half < 2; half++) {
                int row = r0 + half * 8;
                if (row >= M) continue;
                #pragma unroll
                for (int cc = 0; cc < 2; cc++) {
                    int col = cbase + cc;
                    if (col >= N) continue;
                    float v = acc[mi][ni][half * 2 + cc];
                    if (epi == 1) {
                        v += bias[col];
                        v = fmaxf(v, 0.f) + log1pf(expf(-fabsf(v)));
                    } else if (epi == 2) {
                        v += resid[(size_t)row * ldr + col];
                    }
                    C[(size_t)row * ldc + col] = v;
                }
            }
        }
    }
}

// ---------------- causal depthwise conv (k=4) + SiLU -----------------------
__global__ void conv_silu_kernel(const float* __restrict__ xz,
                                 const float* __restrict__ w,
                                 const float* __restrict__ b,
                                 float* __restrict__ out)
{
    int idx = blockIdx.x * blockDim.x + threadIdx.x;
    if (idx >= NTOK * DI) return;
    int d = idx % DI;
    int r = idx / DI;
    int l = r & (SEQL - 1);
    float acc = b[d];
    const float* wd = w + d * 4;
    #pragma unroll
    for (int j = 0; j < 4; j++) {
        int li = l - 3 + j;
        if (li >= 0)
            acc = fmaf(xz[(size_t)(r - 3 + j) * XZW + d], wd[j], acc);
    }
    out[idx] = acc / (1.f + __expf(-acc));   // silu
}

// ---------------- selective scan: 16 lanes per (b,d) -----------------------
__global__ void scan_kernel(const float* __restrict__ dt,
                            const float* __restrict__ xs,
                            const float* __restrict__ xdbl,
                            const float* __restrict__ A_log,
                            float* __restrict__ y)
{
    int b = blockIdx.y;
    int d = blockIdx.x * 16 + (threadIdx.x >> 4);
    int n = threadIdx.x & 15;

    float Adn = -__expf(A_log[d * DS + n]);

    size_t rbase = (size_t)b * SEQL;
    const float* dtp = dt   + rbase * DI + d;
    const float* xsp = xs   + rbase * DI + d;
    const float* Bp  = xdbl + rbase * XD + DTR + n;
    const float* Cp  = xdbl + rbase * XD + DTR + DS + n;
    float*       yp  = y    + rbase * DI + d;

    float h = 0.f;
    for (int l = 0; l < SEQL; l++) {
        float dtv = __ldg(dtp); dtp += DI;
        float xv  = __ldg(xsp); xsp += DI;
        float Bv  = __ldg(Bp);  Bp  += XD;
        float Cv  = __ldg(Cp);  Cp  += XD;
        float a = __expf(dtv * Adn);
        h = fmaf(a, h, dtv * xv * Bv);
        float p = h * Cv;
        p += __shfl_xor_sync(0xffffffffu, p, 8);
        p += __shfl_xor_sync(0xffffffffu, p, 4);
        p += __shfl_xor_sync(0xffffffffu, p, 2);
        p += __shfl_xor_sync(0xffffffffu, p, 1);
        if (n == 0) *yp = p;
        yp += DI;
    }
}

// ---------------- gate: y = (y + xs*Dp) * silu(z) ---------------------------
__global__ void gate_kernel(float* __restrict__ y,
                            const float* __restrict__ xs,
                            const float* __restrict__ xz,
                            const float* __restrict__ Dp)
{
    int idx = blockIdx.x * blockDim.x + threadIdx.x;
    if (idx >= NTOK * DI) return;
    int d = idx % DI;
    int r = idx / DI;
    float z = xz[(size_t)r * XZW + DI + d];
    float s = z / (1.f + __expf(-z));
    y[idx] = fmaf(xs[idx], Dp[d], y[idx]) * s;
}

// ---------------- flip along sequence dimension -----------------------------
__global__ void flip_kernel(const float* __restrict__ in, float* __restrict__ out)
{
    int idx = blockIdx.x * blockDim.x + threadIdx.x;
    if (idx >= NTOK * DM) return;
    int d = idx % DM;
    int r = idx / DM;
    int l = r & (SEQL - 1);
    int b = r / SEQL;
    out[idx] = in[((size_t)b * SEQL + (SEQL - 1 - l)) * DM + d];
}

// ---------------- launcher ---------------------------------------------------
extern "C" void kernel_launch(void* const* d_in, const int* in_sizes, int n_in,
                              void* d_out, int out_size)
{
    const float* x        = (const float*)d_in[0];
    const float* norm_w   = (const float*)d_in[1];
    const float* norm_b   = (const float*)d_in[2];
    const float* in_proj  = (const float*)d_in[3];
    const float* conv_w   = (const float*)d_in[4];
    const float* conv_b   = (const float*)d_in[5];
    const float* x_proj   = (const float*)d_in[6];
    const float* dt_w     = (const float*)d_in[7];
    const float* dt_b     = (const float*)d_in[8];
    const float* A_log    = (const float*)d_in[9];
    const float* Dp       = (const float*)d_in[10];
    const float* out_proj = (const float*)d_in[11];

    float *xn, *xz, *xs, *xdbl, *dt, *y, *h1, *h2;
    cudaGetSymbolAddress((void**)&xn,   g_xn);
    cudaGetSymbolAddress((void**)&xz,   g_xz);
    cudaGetSymbolAddress((void**)&xs,   g_xs);
    cudaGetSymbolAddress((void**)&xdbl, g_xdbl);
    cudaGetSymbolAddress((void**)&dt,   g_dt);
    cudaGetSymbolAddress((void**)&y,    g_y);
    cudaGetSymbolAddress((void**)&h1,   g_h1);
    cudaGetSymbolAddress((void**)&h2,   g_h2);

    const int SMEM_T = 2 * 2 * TBUF * (int)sizeof(float);   // 73728 B
    static int attr_set = 0;
    if (!attr_set) {
        cudaFuncSetAttribute(gemm_tf32,
                             cudaFuncAttributeMaxDynamicSharedMemorySize, SMEM_T);
        attr_set = 1;
    }

    const int EW = 256;

    for (int i = 0; i < 2; i++) {
        const float* cur = (i == 0) ? x : h2;

        // 1. layernorm
        ln_kernel<<<NTOK, 128>>>(cur, norm_w + i * DM, norm_b + i * DM, xn);

        // 2. xz = xn @ in_proj^T   (M=16384, N=1536, K=384)
        {
            dim3 g(XZW / TBN, NTOK / TBM);
            gemm_tf32<<<g, 256, SMEM_T>>>(xn, DM,
                                          in_proj + (size_t)i * XZW * DM, DM,
                                          xz, XZW, nullptr, nullptr, 0,
                                          NTOK, XZW, DM, 0);
        }

        // 3. xs = silu(causal_conv(xz[:, :768]))
        conv_silu_kernel<<<(NTOK * DI + EW - 1) / EW, EW>>>(
            xz, conv_w + (size_t)i * DI * 4, conv_b + i * DI, xs);

        // 4. xdbl = xs @ x_proj^T  (M=16384, N=56, K=768)  [tensor, masked]
        {
            dim3 g(1, NTOK / TBM);
            gemm_tf32<<<g, 256, SMEM_T>>>(xs, DI,
                                          x_proj + (size_t)i * XD * DI, DI,
                                          xdbl, XD, nullptr, nullptr, 0,
                                          NTOK, XD, DI, 0);
        }

        // 5. dt = softplus(xdbl[:, :24] @ dt_w^T + dt_b)  (N=768, K=24)
        {
            dim3 g(DI / TBN, NTOK / TBM);
            gemm_tf32<<<g, 256, SMEM_T>>>(xdbl, XD,
                                          dt_w + (size_t)i * DI * DTR, DTR,
                                          dt, DI, dt_b + i * DI, nullptr, 0,
                                          NTOK, DI, DTR, 1);
        }

        // 6. selective scan -> y
        {
            dim3 g(DI / 16, NB);
            scan_kernel<<<g, 256>>>(dt, xs, xdbl,
                                    A_log + (size_t)i * DI * DS, y);
        }

        // 7. gate: y = (y + xs*Dp) * silu(z)
        gate_kernel<<<(NTOK * DI + EW - 1) / EW, EW>>>(y, xs, xz, Dp + i * DI);

        // 8. out = y @ out_proj^T + cur  (N=384, K=768)
        {
            dim3 g(DM / TBN, NTOK / TBM);
            gemm_tf32<<<g, 256, SMEM_T>>>(y, DI,
                                          out_proj + (size_t)i * DM * DI, DI,
                                          h1, DM, nullptr, cur, DM,
                                          NTOK, DM, DI, 2);
        }

        // 9. flip sequence
        if (i == 0) {
            flip_kernel<<<(NTOK * DM + EW - 1) / EW, EW>>>(h1, h2);
        } else {
            flip_kernel<<<(NTOK * DM + EW - 1) / EW, EW>>>(h1, (float*)d_out);
        }
    }
}

// round 5
// speedup vs baseline: 3.3687x; 1.0793x over previous
#include <cuda_runtime.h>
#include <cuda_bf16.h>
#include <math.h>
#include <stdint.h>

#define NTOK 16384          // BATCH * SEQ
#define SEQL 2048
#define NB   8
#define DM   384
#define DI   768
#define DS   16
#define DTR  24
#define XD   56             // DTR + 2*DS
#define XZW  1536           // 2*DI

// ---------------- scratch (static device memory; no allocation) ------------
__device__ float g_xz  [(size_t)NTOK * XZW];
__device__ float g_xs  [(size_t)NTOK * DI];
__device__ float g_xdbl[(size_t)NTOK * XD];
__device__ float g_dt  [(size_t)NTOK * DI];
__device__ float g_y   [(size_t)NTOK * DI];
__device__ float g_h1  [(size_t)NTOK * DM];
__device__ float g_h2  [(size_t)NTOK * DM];

// bf16 operand copies
__device__ __align__(16) __nv_bfloat16 g_xnb  [(size_t)NTOK * DM];
__device__ __align__(16) __nv_bfloat16 g_xsb  [(size_t)NTOK * DI];
__device__ __align__(16) __nv_bfloat16 g_xdblb[(size_t)NTOK * XD];
__device__ __align__(16) __nv_bfloat16 g_yb   [(size_t)NTOK * DI];
// bf16 weights: in_proj, x_proj, dt_w, out_proj (both layers, contiguous)
#define W_INP  ((size_t)2 * XZW * DM)
#define W_XP   ((size_t)2 * XD * DI)
#define W_DTW  ((size_t)2 * DI * DTR)
#define W_OUTP ((size_t)2 * DM * DI)
__device__ __align__(16) __nv_bfloat16 g_w_inp [W_INP];
__device__ __align__(16) __nv_bfloat16 g_w_xp  [W_XP];
__device__ __align__(16) __nv_bfloat16 g_w_dtw [W_DTW];
__device__ __align__(16) __nv_bfloat16 g_w_outp[W_OUTP];

// ---------------- fp32 -> bf16 conversion ----------------------------------
__global__ void cvt_kernel(const float* __restrict__ src,
                           __nv_bfloat16* __restrict__ dst, int n)
{
    int i = blockIdx.x * blockDim.x + threadIdx.x;
    if (i < n) dst[i] = __float2bfloat16_rn(src[i]);
}

// ---------------- layernorm: one block per token, bf16 output --------------
__global__ void ln_kernel(const float* __restrict__ in,
                          const float* __restrict__ w,
                          const float* __restrict__ b,
                          __nv_bfloat16* __restrict__ out)
{
    int row = blockIdx.x;
    const float* x = in + (size_t)row * DM;
    int t = threadIdx.x;               // 128 threads, 3 elems each
    float v[3];
    float s = 0.f;
    #pragma unroll
    for (int i = 0; i < 3; i++) { v[i] = x[t + i * 128]; s += v[i]; }

    __shared__ float red[4];
    #pragma unroll
    for (int o = 16; o > 0; o >>= 1) s += __shfl_xor_sync(0xffffffffu, s, o);
    if ((t & 31) == 0) red[t >> 5] = s;
    __syncthreads();
    float mu = (red[0] + red[1] + red[2] + red[3]) * (1.f / 384.f);

    float q = 0.f;
    #pragma unroll
    for (int i = 0; i < 3; i++) { float d = v[i] - mu; q = fmaf(d, d, q); }
    #pragma unroll
    for (int o = 16; o > 0; o >>= 1) q += __shfl_xor_sync(0xffffffffu, q, o);
    __syncthreads();
    if ((t & 31) == 0) red[t >> 5] = q;
    __syncthreads();
    float var = (red[0] + red[1] + red[2] + red[3]) * (1.f / 384.f);
    float rs = rsqrtf(var + 1e-5f);

    __nv_bfloat16* o = out + (size_t)row * DM;
    #pragma unroll
    for (int i = 0; i < 3; i++) {
        int c = t + i * 128;
        o[c] = __float2bfloat16_rn((v[i] - mu) * rs * w[c] + b[c]);
    }
}

// ================= BF16 tensor-core NT GEMM (ldmatrix mainloop) =============
// C[m,n] = epi( sum_k A[m,k] * B[n,k] ),  A,B bf16, accum fp32.
// BM=BN=128, BK=32(halfs), 256 threads (8 warps as 2x4), warp tile 64x32.
#define TBM 128
#define TBN 128
#define TBK 32
#define HSTRIDE 40                  // halfs per smem row (80B, conflict-free)
#define TBUFH (TBM * HSTRIDE)       // halfs per A (or B) buffer (5120)

__device__ __forceinline__ void cp_async16(uint32_t dst, const void* src, bool ok)
{
    int sz = ok ? 16 : 0;
    asm volatile("cp.async.cg.shared.global [%0], [%1], 16, %2;\n"
                 :: "r"(dst), "l"(src), "r"(sz));
}
__device__ __forceinline__ void cp_commit() {
    asm volatile("cp.async.commit_group;\n");
}
__device__ __forceinline__ void cp_wait1() {
    asm volatile("cp.async.wait_group 1;\n");
}
__device__ __forceinline__ void ldsm_x4(uint32_t addr, uint32_t& r0, uint32_t& r1,
                                        uint32_t& r2, uint32_t& r3)
{
    asm volatile("ldmatrix.sync.aligned.m8n8.x4.shared.b16 {%0,%1,%2,%3}, [%4];\n"
                 : "=r"(r0), "=r"(r1), "=r"(r2), "=r"(r3) : "r"(addr));
}

// epi: 0 = none, 1 = softplus(v + bias[n]), 2 = v + resid[m*ldr+n]
// Cb: optional bf16 side copy of C
__global__ void __launch_bounds__(256, 2)
gemm_bf16(const __nv_bfloat16* __restrict__ A, int lda,
          const __nv_bfloat16* __restrict__ B, int ldb,
          float* __restrict__ C, int ldc,
          __nv_bfloat16* __restrict__ Cb,
          const float* __restrict__ bias,
          const float* __restrict__ resid, int ldr,
          int M, int N, int K, int epi)
{
    extern __shared__ __nv_bfloat16 smem[];
    __nv_bfloat16* AsB = smem;               // 2 buffers A
    __nv_bfloat16* BsB = smem + 2 * TBUFH;   // 2 buffers B

    int tid  = threadIdx.x;
    int lane = tid & 31;
    int warp = tid >> 5;
    int gid  = lane >> 2;      // 0..7
    int tig  = lane & 3;       // 0..3
    int wm   = (warp >> 2) * 64;   // 0/64
    int wn   = (warp & 3) * 32;    // 0/32/64/96

    int m0 = blockIdx.y * TBM;
    int n0 = blockIdx.x * TBN;
    int nc = (K + TBK - 1) / TBK;

    uint32_t smem_u = (uint32_t)__cvta_generic_to_shared(smem);

    // ldmatrix address bases (bytes); row stride = 80B
    int ar = lane & 15, ahi = lane >> 4;
    uint32_t aBase = smem_u + (uint32_t)((wm + ar) * 80 + ahi * 16);
    int bq = lane >> 3;
    uint32_t bBase = smem_u + (uint32_t)(2 * TBUFH * 2)
                   + (uint32_t)((wn + (bq >> 1) * 8 + (lane & 7)) * 80
                                + (bq & 1) * 16);

    float acc[4][4][4];
    #pragma unroll
    for (int i = 0; i < 4; i++)
        #pragma unroll
        for (int j = 0; j < 4; j++)
            #pragma unroll
            for (int c = 0; c < 4; c++) acc[i][j][c] = 0.f;

    // per chunk: A tile 128x32 halfs = 512 x 16B slots; 2 per thread per tile
    auto load_tiles = [&](int buf, int chunk) {
        int k0 = chunk * TBK;
        __nv_bfloat16* Asb = AsB + buf * TBUFH;
        __nv_bfloat16* Bsb = BsB + buf * TBUFH;
        #pragma unroll
        for (int it = 0; it < 2; it++) {
            int idx = tid + it * 256;
            int m  = idx >> 2;
            int k8 = idx & 3;
            int gk = k0 + k8 * 8;
            bool kok = (gk < K);
            {
                int gm = m0 + m;
                const void* src = kok ? (const void*)(A + (size_t)gm * lda + gk)
                                      : (const void*)A;
                uint32_t dst = (uint32_t)__cvta_generic_to_shared(
                                    Asb + m * HSTRIDE + k8 * 8);
                cp_async16(dst, src, kok);
            }
            {
                int gn = n0 + m;
                bool ok = kok && (gn < N);
                const void* src = ok ? (const void*)(B + (size_t)gn * ldb + gk)
                                     : (const void*)B;
                uint32_t dst = (uint32_t)__cvta_generic_to_shared(
                                    Bsb + m * HSTRIDE + k8 * 8);
                cp_async16(dst, src, ok);
            }
        }
    };

    load_tiles(0, 0);
    cp_commit();

    for (int c = 0; c < nc; c++) {
        if (c + 1 < nc) load_tiles((c + 1) & 1, c + 1);
        cp_commit();
        cp_wait1();
        __syncthreads();

        uint32_t bufOff = (uint32_t)((c & 1) * TBUFH * 2);
        uint32_t aB = aBase + bufOff;
        uint32_t bB = bBase + bufOff;

        #pragma unroll
        for (int kk = 0; kk < 2; kk++) {
            uint32_t kOff = kk * 32;   // 16 halfs = 32 bytes
            uint32_t af[4][4];
            #pragma unroll
            for (int mi = 0; mi < 4; mi++)
                ldsm_x4(aB + (uint32_t)(mi * 16 * 80) + kOff,
                        af[mi][0], af[mi][1], af[mi][2], af[mi][3]);
            uint32_t bf[4][2];
            #pragma unroll
            for (int p = 0; p < 2; p++)
                ldsm_x4(bB + (uint32_t)(p * 16 * 80) + kOff,
                        bf[2*p][0], bf[2*p][1], bf[2*p+1][0], bf[2*p+1][1]);
            #pragma unroll
            for (int mi = 0; mi < 4; mi++)
                #pragma unroll
                for (int ni = 0; ni < 4; ni++) {
                    asm volatile(
                        "mma.sync.aligned.m16n8k16.row.col.f32.bf16.bf16.f32 "
                        "{%0,%1,%2,%3}, {%4,%5,%6,%7}, {%8,%9}, {%0,%1,%2,%3};\n"
                        : "+f"(acc[mi][ni][0]), "+f"(acc[mi][ni][1]),
                          "+f"(acc[mi][ni][2]), "+f"(acc[mi][ni][3])
                        : "r"(af[mi][0]), "r"(af[mi][1]),
                          "r"(af[mi][2]), "r"(af[mi][3]),
                          "r"(bf[ni][0]), "r"(bf[ni][1]));
                }
        }
        __syncthreads();
    }

    // epilogue
    #pragma unroll
    for (int mi = 0; mi < 4; mi++) {
        int r0 = m0 + wm + mi * 16 + gid;
        #pragma unroll
        for (int ni = 0; ni < 4; ni++) {
            int cbase = n0 + wn + ni * 8 + tig * 2;
            #pragma unroll
            for (int half = 0; half < 2; half++) {
                int row = r0 + half * 8;
                if (row >= M) continue;
                #pragma unroll
                for (int cc = 0; cc < 2; cc++) {
                    int col = cbase + cc;
                    if (col >= N) continue;
                    float v = acc[mi][ni][half * 2 + cc];
                    if (epi == 1) {
                        v += bias[col];
                        v = fmaxf(v, 0.f) + log1pf(expf(-fabsf(v)));
                    } else if (epi == 2) {
                        v += resid[(size_t)row * ldr + col];
                    }
                    C[(size_t)row * ldc + col] = v;
                    if (Cb) Cb[(size_t)row * ldc + col] = __float2bfloat16_rn(v);
                }
            }
        }
    }
}

// ---------------- causal depthwise conv (k=4) + SiLU (fp32 + bf16 out) -----
__global__ void conv_silu_kernel(const float* __restrict__ xz,
                                 const float* __restrict__ w,
                                 const float* __restrict__ b,
                                 float* __restrict__ out,
                                 __nv_bfloat16* __restrict__ outb)
{
    int idx = blockIdx.x * blockDim.x + threadIdx.x;
    if (idx >= NTOK * DI) return;
    int d = idx % DI;
    int r = idx / DI;
    int l = r & (SEQL - 1);
    float acc = b[d];
    const float* wd = w + d * 4;
    #pragma unroll
    for (int j = 0; j < 4; j++) {
        int li = l - 3 + j;
        if (li >= 0)
            acc = fmaf(xz[(size_t)(r - 3 + j) * XZW + d], wd[j], acc);
    }
    float v = acc / (1.f + __expf(-acc));   // silu
    out[idx] = v;
    outb[idx] = __float2bfloat16_rn(v);
}

// ---------------- selective scan: 16 lanes per (b,d) -----------------------
__global__ void scan_kernel(const float* __restrict__ dt,
                            const float* __restrict__ xs,
                            const float* __restrict__ xdbl,
                            const float* __restrict__ A_log,
                            float* __restrict__ y)
{
    int b = blockIdx.y;
    int d = blockIdx.x * 16 + (threadIdx.x >> 4);
    int n = threadIdx.x & 15;

    float Adn = -__expf(A_log[d * DS + n]);

    size_t rbase = (size_t)b * SEQL;
    const float* dtp = dt   + rbase * DI + d;
    const float* xsp = xs   + rbase * DI + d;
    const float* Bp  = xdbl + rbase * XD + DTR + n;
    const float* Cp  = xdbl + rbase * XD + DTR + DS + n;
    float*       yp  = y    + rbase * DI + d;

    float h = 0.f;
    for (int l = 0; l < SEQL; l++) {
        float dtv = __ldg(dtp); dtp += DI;
        float xv  = __ldg(xsp); xsp += DI;
        float Bv  = __ldg(Bp);  Bp  += XD;
        float Cv  = __ldg(Cp);  Cp  += XD;
        float a = __expf(dtv * Adn);
        h = fmaf(a, h, dtv * xv * Bv);
        float p = h * Cv;
        p += __shfl_xor_sync(0xffffffffu, p, 8);
        p += __shfl_xor_sync(0xffffffffu, p, 4);
        p += __shfl_xor_sync(0xffffffffu, p, 2);
        p += __shfl_xor_sync(0xffffffffu, p, 1);
        if (n == 0) *yp = p;
        yp += DI;
    }
}

// ---------------- gate: yb = bf16((y + xs*Dp) * silu(z)) --------------------
__global__ void gate_kernel(const float* __restrict__ y,
                            const float* __restrict__ xs,
                            const float* __restrict__ xz,
                            const float* __restrict__ Dp,
                            __nv_bfloat16* __restrict__ yb)
{
    int idx = blockIdx.x * blockDim.x + threadIdx.x;
    if (idx >= NTOK * DI) return;
    int d = idx % DI;
    int r = idx / DI;
    float z = xz[(size_t)r * XZW + DI + d];
    float s = z / (1.f + __expf(-z));
    yb[idx] = __float2bfloat16_rn(fmaf(xs[idx], Dp[d], y[idx]) * s);
}

// ---------------- flip along sequence dimension -----------------------------
__global__ void flip_kernel(const float* __restrict__ in, float* __restrict__ out)
{
    int idx = blockIdx.x * blockDim.x + threadIdx.x;
    if (idx >= NTOK * DM) return;
    int d = idx % DM;
    int r = idx / DM;
    int l = r & (SEQL - 1);
    int b = r / SEQL;
    out[idx] = in[((size_t)b * SEQL + (SEQL - 1 - l)) * DM + d];
}

// ---------------- launcher ---------------------------------------------------
extern "C" void kernel_launch(void* const* d_in, const int* in_sizes, int n_in,
                              void* d_out, int out_size)
{
    const float* x        = (const float*)d_in[0];
    const float* norm_w   = (const float*)d_in[1];
    const float* norm_b   = (const float*)d_in[2];
    const float* in_proj  = (const float*)d_in[3];
    const float* conv_w   = (const float*)d_in[4];
    const float* conv_b   = (const float*)d_in[5];
    const float* x_proj   = (const float*)d_in[6];
    const float* dt_w     = (const float*)d_in[7];
    const float* dt_b     = (const float*)d_in[8];
    const float* A_log    = (const float*)d_in[9];
    const float* Dp       = (const float*)d_in[10];
    const float* out_proj = (const float*)d_in[11];

    float *xz, *xs, *xdbl, *dt, *y, *h1, *h2;
    __nv_bfloat16 *xnb, *xsb, *xdblb, *yb, *w_inp, *w_xp, *w_dtw, *w_outp;
    cudaGetSymbolAddress((void**)&xz,    g_xz);
    cudaGetSymbolAddress((void**)&xs,    g_xs);
    cudaGetSymbolAddress((void**)&xdbl,  g_xdbl);
    cudaGetSymbolAddress((void**)&dt,    g_dt);
    cudaGetSymbolAddress((void**)&y,     g_y);
    cudaGetSymbolAddress((void**)&h1,    g_h1);
    cudaGetSymbolAddress((void**)&h2,    g_h2);
    cudaGetSymbolAddress((void**)&xnb,   g_xnb);
    cudaGetSymbolAddress((void**)&xsb,   g_xsb);
    cudaGetSymbolAddress((void**)&xdblb, g_xdblb);
    cudaGetSymbolAddress((void**)&yb,    g_yb);
    cudaGetSymbolAddress((void**)&w_inp, g_w_inp);
    cudaGetSymbolAddress((void**)&w_xp,  g_w_xp);
    cudaGetSymbolAddress((void**)&w_dtw, g_w_dtw);
    cudaGetSymbolAddress((void**)&w_outp,g_w_outp);

    const int SMEM_T = 4 * TBUFH * (int)sizeof(__nv_bfloat16);   // 40960 B
    static int attr_set = 0;
    if (!attr_set) {
        cudaFuncSetAttribute(gemm_bf16,
                             cudaFuncAttributeMaxDynamicSharedMemorySize, SMEM_T);
        attr_set = 1;
    }

    const int EW = 256;

    // weight conversion (both layers each)
    cvt_kernel<<<((int)W_INP  + EW - 1) / EW, EW>>>(in_proj,  w_inp,  (int)W_INP);
    cvt_kernel<<<((int)W_XP   + EW - 1) / EW, EW>>>(x_proj,   w_xp,   (int)W_XP);
    cvt_kernel<<<((int)W_DTW  + EW - 1) / EW, EW>>>(dt_w,     w_dtw,  (int)W_DTW);
    cvt_kernel<<<((int)W_OUTP + EW - 1) / EW, EW>>>(out_proj, w_outp, (int)W_OUTP);

    for (int i = 0; i < 2; i++) {
        const float* cur = (i == 0) ? x : h2;

        // 1. layernorm -> bf16 xn
        ln_kernel<<<NTOK, 128>>>(cur, norm_w + i * DM, norm_b + i * DM, xnb);

        // 2. xz = xn @ in_proj^T   (M=16384, N=1536, K=384)
        {
            dim3 g(XZW / TBN, NTOK / TBM);
            gemm_bf16<<<g, 256, SMEM_T>>>(xnb, DM,
                                          w_inp + (size_t)i * XZW * DM, DM,
                                          xz, XZW, nullptr, nullptr, nullptr, 0,
                                          NTOK, XZW, DM, 0);
        }

        // 3. xs = silu(causal_conv(xz[:, :768]))  (fp32 + bf16)
        conv_silu_kernel<<<(NTOK * DI + EW - 1) / EW, EW>>>(
            xz, conv_w + (size_t)i * DI * 4, conv_b + i * DI, xs, xsb);

        // 4. xdbl = xs @ x_proj^T  (M=16384, N=56, K=768) -> fp32 + bf16
        {
            dim3 g(1, NTOK / TBM);
            gemm_bf16<<<g, 256, SMEM_T>>>(xsb, DI,
                                          w_xp + (size_t)i * XD * DI, DI,
                                          xdbl, XD, xdblb, nullptr, nullptr, 0,
                                          NTOK, XD, DI, 0);
        }

        // 5. dt = softplus(xdbl[:, :24] @ dt_w^T + dt_b)  (N=768, K=24)
        {
            dim3 g(DI / TBN, NTOK / TBM);
            gemm_bf16<<<g, 256, SMEM_T>>>(xdblb, XD,
                                          w_dtw + (size_t)i * DI * DTR, DTR,
                                          dt, DI, nullptr, dt_b + i * DI,
                                          nullptr, 0,
                                          NTOK, DI, DTR, 1);
        }

        // 6. selective scan -> y (fp32)
        {
            dim3 g(DI / 16, NB);
            scan_kernel<<<g, 256>>>(dt, xs, xdbl,
                                    A_log + (size_t)i * DI * DS, y);
        }

        // 7. gate -> bf16 yb
        gate_kernel<<<(NTOK * DI + EW - 1) / EW, EW>>>(y, xs, xz,
                                                       Dp + i * DI, yb);

        // 8. out = yb @ out_proj^T + cur  (N=384, K=768)
        {
            dim3 g(DM / TBN, NTOK / TBM);
            gemm_bf16<<<g, 256, SMEM_T>>>(yb, DI,
                                          w_outp + (size_t)i * DM * DI, DI,
                                          h1, DM, nullptr, nullptr, cur, DM,
                                          NTOK, DM, DI, 2);
        }

        // 9. flip sequence
        if (i == 0) {
            flip_kernel<<<(NTOK * DM + EW - 1) / EW, EW>>>(h1, h2);
        } else {
            flip_kernel<<<(NTOK * DM + EW - 1) / EW, EW>>>(h1, (float*)d_out);
        }
    }
}